// round 12
// baseline (speedup 1.0000x reference)
#include <cuda_runtime.h>

#define BB 32
#define TT 2048
#define DD 1024
#define CHUNK 64   // rows per block (8 warps x 8 rows)

// Device scratch (no allocation allowed in kernel_launch).
// g_ctx is zero-initialized at module load; finalize_kernel re-zeroes it after
// consuming, so every graph replay starts from zeros. Deterministic.
__device__ float g_exp[BB * TT];
__device__ float g_ctx[BB * DD];

__device__ __forceinline__ float fast_tanh(float x) {
    float y;
    asm("tanh.approx.f32 %0, %1;" : "=f"(y) : "f"(x));
    return y;
}

// ---------------------------------------------------------------------------
// Fused kernel (unchanged from R11 — measured ~67us, ~5.7TB/s):
// one block owns a 64-row chunk of batch b.
// Phase 1: warp-per-row, e_t = v . tanh(k+q+wf), wexp = exp(e_t)
//   (no max subtraction: |e| <= sum|v| ~ 27, fp32-safe) -> smem + g_exp.
// Phase 2: each thread owns one float4 of D, accumulates sum_t wexp_t*value[t],
//   single atomic flush into g_ctx. Masked chunks exit before any barrier.
// ---------------------------------------------------------------------------
__global__ void __launch_bounds__(256) fused_kernel(
    const float* __restrict__ keys,
    const float* __restrict__ query,
    const float* __restrict__ wf,
    const float* __restrict__ v,
    const float* __restrict__ value,
    const int* __restrict__ lens)
{
    const int b   = blockIdx.y;
    const int len = __ldg(lens + b);
    const int t0  = blockIdx.x * CHUNK;
    if (t0 >= len) return;
    const int tend = min(t0 + CHUNK, len);

    __shared__ float s_exp[CHUNK];

    const int warp = threadIdx.x >> 5;
    const int lane = threadIdx.x & 31;
    const float4* q4 = reinterpret_cast<const float4*>(query + (size_t)b * DD);
    const float4* v4 = reinterpret_cast<const float4*>(v);

    // ---------- Phase 1: energies -> exp ----------
    #pragma unroll
    for (int k = 0; k < CHUNK / 8; ++k) {
        const int t = t0 + warp + 8 * k;       // stride-8: warp w does rows w, w+8, ...
        if (t < tend) {
            const size_t row = ((size_t)b * TT + t) * DD;
            const float4* k4 = reinterpret_cast<const float4*>(keys + row);
            const float4* f4 = reinterpret_cast<const float4*>(wf + row);

            float s = 0.0f;
            #pragma unroll
            for (int j = 0; j < 8; ++j) {
                const int idx = lane + 32 * j;
                float4 kk = k4[idx];
                float4 ff = f4[idx];
                float4 qq = __ldg(q4 + idx);
                float4 vv = __ldg(v4 + idx);
                s += vv.x * fast_tanh(kk.x + qq.x + ff.x)
                   + vv.y * fast_tanh(kk.y + qq.y + ff.y)
                   + vv.z * fast_tanh(kk.z + qq.z + ff.z)
                   + vv.w * fast_tanh(kk.w + qq.w + ff.w);
            }
            #pragma unroll
            for (int o = 16; o; o >>= 1) s += __shfl_xor_sync(0xffffffffu, s, o);

            if (lane == 0) {
                const float wexp = __expf(s);
                s_exp[t - t0] = wexp;
                g_exp[b * TT + t] = wexp;
            }
        }
    }
    __syncthreads();

    // ---------- Phase 2: weighted value accumulation ----------
    const int i = threadIdx.x;                 // one float4 of D per thread
    float4 acc = make_float4(0.f, 0.f, 0.f, 0.f);
    const float4* vb = reinterpret_cast<const float4*>(value)
                     + ((size_t)b * TT + t0) * (DD / 4);

    #pragma unroll 8
    for (int t = t0; t < tend; ++t) {
        const float w = s_exp[t - t0];
        float4 vv = __ldcs(vb + i);
        acc.x += w * vv.x;
        acc.y += w * vv.y;
        acc.z += w * vv.z;
        acc.w += w * vv.w;
        vb += DD / 4;
    }

    float* ctx = g_ctx + (size_t)b * DD + i * 4;
    atomicAdd(ctx + 0, acc.x);
    atomicAdd(ctx + 1, acc.y);
    atomicAdd(ctx + 2, acc.z);
    atomicAdd(ctx + 3, acc.w);
}

// ---------------------------------------------------------------------------
// Finalize (parallel rebuild): grid (9, BB) = 288 blocks. Each block
// independently recomputes S_b from L2-resident g_exp (redundant but state-free
// and latency-cheap), then:
//   seg 0..7 : write one 256-wide slice of the normalized weights row
//   seg 8    : normalize the context (float4) and re-zero g_ctx for next replay
// ---------------------------------------------------------------------------
__global__ void __launch_bounds__(256) finalize_kernel(
    const int* __restrict__ lens,
    float* __restrict__ out)
{
    const int b   = blockIdx.y;
    const int seg = blockIdx.x;               // 0..8
    const int len = __ldg(lens + b);
    const float* e = g_exp + b * TT;
    const int tid = threadIdx.x;

    __shared__ float red[8];
    __shared__ float s_sum;

    // ---- per-block recompute of S_b (L2-resident) ----
    float s = 0.f;
    #pragma unroll
    for (int j = 0; j < TT / 256; ++j) {
        const int t = tid + 256 * j;
        if (t < len) s += e[t];
    }
    #pragma unroll
    for (int o = 16; o; o >>= 1) s += __shfl_xor_sync(0xffffffffu, s, o);
    if ((tid & 31) == 0) red[tid >> 5] = s;
    __syncthreads();
    if (tid == 0) {
        float ss = red[0];
        #pragma unroll
        for (int j = 1; j < 8; j++) ss += red[j];
        s_sum = ss;
    }
    __syncthreads();
    const float inv = 1.0f / s_sum;

    if (seg < 8) {
        // ---- weights slice ----
        const int t = seg * 256 + tid;
        float* wout = out + (size_t)BB * DD + (size_t)b * TT;
        wout[t] = (t < len) ? e[t] * inv : 0.0f;
    } else {
        // ---- context normalize + re-zero accumulator ----
        float4* cout = reinterpret_cast<float4*>(out + (size_t)b * DD);
        float4* gctx = reinterpret_cast<float4*>(g_ctx + (size_t)b * DD);
        float4 c = gctx[tid];
        c.x *= inv; c.y *= inv; c.z *= inv; c.w *= inv;
        cout[tid] = c;
        gctx[tid] = make_float4(0.f, 0.f, 0.f, 0.f);  // restore replay invariant
    }
}

// ---------------------------------------------------------------------------
extern "C" void kernel_launch(void* const* d_in, const int* in_sizes, int n_in,
                              void* d_out, int out_size)
{
    const float* keys  = (const float*)d_in[0];
    const float* value = (const float*)d_in[1];
    const float* query = (const float*)d_in[2];
    const float* wf    = (const float*)d_in[3];
    const float* v     = (const float*)d_in[4];
    const int*   lens  = (const int*)d_in[5];
    float* out = (float*)d_out;

    fused_kernel<<<dim3(TT / CHUNK, BB), 256>>>(keys, query, wf, v, value, lens);
    finalize_kernel<<<dim3(9, BB), 256>>>(lens, out);
}

// round 13
// speedup vs baseline: 1.1039x; 1.1039x over previous
#include <cuda_runtime.h>

#define BB 32
#define TT 2048
#define DD 1024
#define CHUNK 64   // rows per block (8 warps x 8 rows)

// Device scratch (no allocation allowed in kernel_launch).
// g_ctx and g_count are zero-initialized at module load; the finalizer block
// re-zeroes them after consuming, so every graph replay starts from zeros.
__device__ float g_exp[BB * TT];
__device__ float g_ctx[BB * DD];
__device__ int   g_count[BB];

__device__ __forceinline__ float fast_tanh(float x) {
    float y;
    asm("tanh.approx.f32 %0, %1;" : "=f"(y) : "f"(x));
    return y;
}

// ---------------------------------------------------------------------------
// Single fused kernel. One block owns a 64-row chunk of batch b.
// Phase 1: warp-per-row, e_t = v . tanh(k+q+wf), wexp = exp(e_t)
//   (no max subtraction: |e| <= sum|v| ~ 27, fp32-safe) -> smem + g_exp.
// Phase 2: each thread owns one float4 of D, accumulates sum_t wexp_t*value[t],
//   single atomic flush into g_ctx.
// Phase 3 (last-arriving block of each batch only): S_b = sum exps, write
//   normalized weights + context to d_out, re-zero g_ctx/g_count.
// Masked chunks exit before any barrier; active-block count = ceil(len/64).
// ---------------------------------------------------------------------------
__global__ void __launch_bounds__(256) fused_kernel(
    const float* __restrict__ keys,
    const float* __restrict__ query,
    const float* __restrict__ wf,
    const float* __restrict__ v,
    const float* __restrict__ value,
    const int* __restrict__ lens,
    float* __restrict__ out)
{
    const int b   = blockIdx.y;
    const int len = __ldg(lens + b);
    const int t0  = blockIdx.x * CHUNK;
    if (t0 >= len) return;
    const int tend = min(t0 + CHUNK, len);

    __shared__ float s_exp[CHUNK];
    __shared__ int   s_last;

    const int warp = threadIdx.x >> 5;
    const int lane = threadIdx.x & 31;
    const int tid  = threadIdx.x;
    const float4* q4 = reinterpret_cast<const float4*>(query + (size_t)b * DD);
    const float4* v4 = reinterpret_cast<const float4*>(v);

    // ---------- Phase 1: energies -> exp ----------
    #pragma unroll
    for (int k = 0; k < CHUNK / 8; ++k) {
        const int t = t0 + warp + 8 * k;
        if (t < tend) {
            const size_t row = ((size_t)b * TT + t) * DD;
            const float4* k4 = reinterpret_cast<const float4*>(keys + row);
            const float4* f4 = reinterpret_cast<const float4*>(wf + row);

            float s = 0.0f;
            #pragma unroll
            for (int j = 0; j < 8; ++j) {
                const int idx = lane + 32 * j;
                float4 kk = k4[idx];
                float4 ff = f4[idx];
                float4 qq = __ldg(q4 + idx);
                float4 vv = __ldg(v4 + idx);
                s += vv.x * fast_tanh(kk.x + qq.x + ff.x)
                   + vv.y * fast_tanh(kk.y + qq.y + ff.y)
                   + vv.z * fast_tanh(kk.z + qq.z + ff.z)
                   + vv.w * fast_tanh(kk.w + qq.w + ff.w);
            }
            #pragma unroll
            for (int o = 16; o; o >>= 1) s += __shfl_xor_sync(0xffffffffu, s, o);

            if (lane == 0) {
                const float wexp = __expf(s);
                s_exp[t - t0] = wexp;
                g_exp[b * TT + t] = wexp;
            }
        }
    }
    __syncthreads();

    // ---------- Phase 2: weighted value accumulation ----------
    float4 acc = make_float4(0.f, 0.f, 0.f, 0.f);
    const float4* vb = reinterpret_cast<const float4*>(value)
                     + ((size_t)b * TT + t0) * (DD / 4);

    #pragma unroll 8
    for (int t = t0; t < tend; ++t) {
        const float w = s_exp[t - t0];
        float4 vv = __ldcs(vb + tid);
        acc.x += w * vv.x;
        acc.y += w * vv.y;
        acc.z += w * vv.z;
        acc.w += w * vv.w;
        vb += DD / 4;
    }

    float* ctx = g_ctx + (size_t)b * DD + tid * 4;
    atomicAdd(ctx + 0, acc.x);
    atomicAdd(ctx + 1, acc.y);
    atomicAdd(ctx + 2, acc.z);
    atomicAdd(ctx + 3, acc.w);

    // ---------- Phase 3: last active block of batch b finalizes ----------
    __threadfence();
    __syncthreads();
    if (tid == 0) {
        const int nblk = (len + CHUNK - 1) / CHUNK;
        s_last = (atomicAdd(&g_count[b], 1) == nblk - 1) ? 1 : 0;
    }
    __syncthreads();
    if (!s_last) return;
    __threadfence();   // ensure we observe all other blocks' g_ctx/g_exp writes

    const float* e = g_exp + b * TT;

    // S_b = sum of exps (L2-resident)
    __shared__ float red[8];
    __shared__ float s_sum;
    float s = 0.f;
    #pragma unroll
    for (int j = 0; j < TT / 256; ++j) {
        const int t = tid + 256 * j;
        if (t < len) s += e[t];
    }
    #pragma unroll
    for (int o = 16; o; o >>= 1) s += __shfl_xor_sync(0xffffffffu, s, o);
    if ((tid & 31) == 0) red[tid >> 5] = s;
    __syncthreads();
    if (tid == 0) {
        float ss = red[0];
        #pragma unroll
        for (int j = 1; j < 8; j++) ss += red[j];
        s_sum = ss;
    }
    __syncthreads();
    const float inv = 1.0f / s_sum;

    // normalized weights (0 for masked t)
    float* wout = out + (size_t)BB * DD + (size_t)b * TT;
    #pragma unroll
    for (int j = 0; j < TT / 256; ++j) {
        const int t = tid + 256 * j;
        wout[t] = (t < len) ? e[t] * inv : 0.0f;
    }

    // normalized context + restore replay invariants
    float4* cout = reinterpret_cast<float4*>(out + (size_t)b * DD);
    float4* gctx = reinterpret_cast<float4*>(g_ctx + (size_t)b * DD);
    float4 c = gctx[tid];
    c.x *= inv; c.y *= inv; c.z *= inv; c.w *= inv;
    cout[tid] = c;
    gctx[tid] = make_float4(0.f, 0.f, 0.f, 0.f);
    if (tid == 0) g_count[b] = 0;
}

// ---------------------------------------------------------------------------
extern "C" void kernel_launch(void* const* d_in, const int* in_sizes, int n_in,
                              void* d_out, int out_size)
{
    const float* keys  = (const float*)d_in[0];
    const float* value = (const float*)d_in[1];
    const float* query = (const float*)d_in[2];
    const float* wf    = (const float*)d_in[3];
    const float* v     = (const float*)d_in[4];
    const int*   lens  = (const int*)d_in[5];
    float* out = (float*)d_out;

    fused_kernel<<<dim3(TT / CHUNK, BB), 256>>>(keys, query, wf, v, value, lens, out);
}